// round 13
// baseline (speedup 1.0000x reference)
#include <cuda_runtime.h>

// DistMult edge scoring, R13: R12 (tile-local counting sort by relation)
// with the processing-loop bound fixed (each warp owns QPW=8 quads, not 2).
//   out[e] = sigmoid( sum_d h[src[e]][d] * W[rel[e]][d] * h[dst[e]][d] )
//
// R8-R11 pin at 13.4 L1-wf-cyc/edge; ~3.4 of that is W gathers (4 random
// relations per warp). Sorting each 256-edge tile by r in smem gives warps
// runs of equal r: the four 8-lane groups read IDENTICAL W addresses
// (broadcast) -> W ~1.1 wf/edge. Index loads and stores also coalesce.
// Target ledger ~10.8 wf-cyc/edge.

#define TPB 256
#define TILE 256
#define QPW ((TILE / 4) / (TPB / 32))   // quads per warp = 8
#define GRID_BLOCKS (148 * 8)

__global__ __launch_bounds__(TPB, 7)
void distmult_kernel(const float* __restrict__ h,
                     const float* __restrict__ W,
                     const int* __restrict__ src,
                     const int* __restrict__ dst,
                     const int* __restrict__ rel,
                     float* __restrict__ out,
                     int E)
{
    __shared__ int4  s_sorted[TILE];   // {src, dst, tile-local id, rel}
    __shared__ float s_res[TILE];
    __shared__ int   s_hist[6], s_base[6], s_cur[6];

    const int t    = threadIdx.x;
    const int lane = t & 31;
    const int warp = t >> 5;
    const int sub  = lane & 7;    // lane within 8-lane edge group
    const int grp  = lane >> 3;   // which of 4 edges in the quad

    const float4* __restrict__ h4 = reinterpret_cast<const float4*>(h);
    const float4* __restrict__ W4 = reinterpret_cast<const float4*>(W);

    const int ntiles = (E + TILE - 1) / TILE;

    for (int tile = blockIdx.x; tile < ntiles; tile += gridDim.x) {
        const int base = tile * TILE;
        const int cnt  = min(TILE, E - base);

        // ---- load (coalesced) + histogram ----
        if (t < 6) { s_hist[t] = 0; s_cur[t] = 0; }
        __syncthreads();                       // orders prev-tile reads too

        int es = 0, ed = 0, er = 0;
        const bool valid = t < cnt;
        if (valid) {
            es = __ldg(src + base + t);
            ed = __ldg(dst + base + t);
            er = __ldg(rel + base + t);
            atomicAdd(&s_hist[er], 1);
        }
        __syncthreads();

        if (t == 0) {
            int acc = 0;
            #pragma unroll
            for (int i = 0; i < 6; i++) { s_base[i] = acc; acc += s_hist[i]; }
        }
        __syncthreads();

        if (valid) {
            int pos = s_base[er] + atomicAdd(&s_cur[er], 1);
            s_sorted[pos] = make_int4(es, ed, t, er);
        }
        __syncthreads();

        // ---- process: warp w owns sorted edges [w*32, w*32+32), 4/iter ----
        const int nq = (cnt + 3) >> 2;
        #pragma unroll 1
        for (int qi = 0; qi < QPW; qi++) {
            int q = warp * QPW + qi;
            if (q >= nq) break;

            int idx  = q * 4 + grp;
            int idxc = idx < cnt ? idx : cnt - 1;   // clamp (dup compute ok)
            int4 pk  = s_sorted[idxc];

            const float4* __restrict__ up = h4 + pk.x * 32 + sub;
            const float4* __restrict__ vp = h4 + pk.y * 32 + sub;
            const float4* __restrict__ wp = W4 + pk.w * 32 + sub;

            // Phase 1: float4 positions sub, sub+8 (6 loads batched)
            float4 u0 = __ldg(up);
            float4 u1 = __ldg(up + 8);
            float4 v0 = __ldg(vp);
            float4 v1 = __ldg(vp + 8);
            float4 w0 = __ldg(wp);
            float4 w1 = __ldg(wp + 8);

            float sum = u0.x * w0.x * v0.x
                      + u0.y * w0.y * v0.y
                      + u0.z * w0.z * v0.z
                      + u0.w * w0.w * v0.w
                      + u1.x * w1.x * v1.x
                      + u1.y * w1.y * v1.y
                      + u1.z * w1.z * v1.z
                      + u1.w * w1.w * v1.w;

            // Phase 2: float4 positions sub+16, sub+24
            u0 = __ldg(up + 16);
            u1 = __ldg(up + 24);
            v0 = __ldg(vp + 16);
            v1 = __ldg(vp + 24);
            w0 = __ldg(wp + 16);
            w1 = __ldg(wp + 24);

            sum += u0.x * w0.x * v0.x
                 + u0.y * w0.y * v0.y
                 + u0.z * w0.z * v0.z
                 + u0.w * w0.w * v0.w
                 + u1.x * w1.x * v1.x
                 + u1.y * w1.y * v1.y
                 + u1.z * w1.z * v1.z
                 + u1.w * w1.w * v1.w;

            #pragma unroll
            for (int off = 4; off > 0; off >>= 1)
                sum += __shfl_xor_sync(0xffffffffu, sum, off);

            if (sub == 0 && idx < cnt)
                s_res[pk.z] = 1.0f / (1.0f + __expf(-sum));
        }
        __syncthreads();

        // ---- coalesced store ----
        if (valid)
            out[base + t] = s_res[t];
    }
}

extern "C" void kernel_launch(void* const* d_in, const int* in_sizes, int n_in,
                              void* d_out, int out_size)
{
    const float* h   = (const float*)d_in[0];
    const float* W   = (const float*)d_in[1];
    const int*   src = (const int*)d_in[2];
    const int*   dst = (const int*)d_in[3];
    const int*   rel = (const int*)d_in[4];
    float* out = (float*)d_out;

    int E = in_sizes[2];
    if (E <= 0) return;

    int ntiles = (E + TILE - 1) / TILE;
    int blocks = ntiles < GRID_BLOCKS ? ntiles : GRID_BLOCKS;
    if (blocks < 1) blocks = 1;
    distmult_kernel<<<blocks, TPB>>>(h, W, src, dst, rel, out, E);
}

// round 16
// speedup vs baseline: 1.1673x; 1.1673x over previous
#include <cuda_runtime.h>

// DistMult edge scoring, R16 (= R14/R15 resubmit; broker failed twice,
// kernel never executed): register-only warp sort by relation
// (ballot + __fns + shuffle), then the proven R11 quad body.
//   out[e] = sigmoid( sum_d h[src[e]][d] * W[rel[e]][d] * h[dst[e]][d] )
//
// R7/R13 lesson: sort by r pays only if the sort itself is ~free. Each warp
// sorts its 32-edge chunk in registers: 6 ballots -> bin counts; each lane
// finds the source lane of its sorted slot via popc/__fns; 3 shuffles gather
// (s, d, pack{e<<3|r}). Per quad, 3 broadcast shuffles replace the 3 index
// loads (wash); W rows become runs -> E[distinct r per quad] ~1.56 vs 3.13
// -> W wavefronts halve. No smem, no atomics, no extra barriers.

#define WPB 8
#define TPB (WPB * 32)
#define GRID_BLOCKS (148 * 8)
#define FULL 0xffffffffu

__global__ __launch_bounds__(TPB, 7)
void distmult_kernel(const float* __restrict__ h,
                     const float* __restrict__ W,
                     const int* __restrict__ src,
                     const int* __restrict__ dst,
                     const int* __restrict__ rel,
                     float* __restrict__ out,
                     int E)
{
    const int lane = threadIdx.x & 31;
    const int sub  = lane & 7;    // lane within 8-lane edge group
    const int grp  = lane >> 3;   // which of 4 edges per iteration

    const float4* __restrict__ h4 = reinterpret_cast<const float4*>(h);
    const float4* __restrict__ W4 = reinterpret_cast<const float4*>(W);

    const int warp_glb  = blockIdx.x * WPB + (threadIdx.x >> 5);
    const int warp_step = gridDim.x * WPB;
    const int nchunks   = (E + 31) >> 5;   // 32 edges per warp-chunk

    for (int c = warp_glb; c < nchunks; c += warp_step) {
        const int base = c << 5;
        int e  = base + lane;
        int ec = e < E ? e : E - 1;        // tail clamp (dup edges benign)

        int s = __ldg(src + ec);
        int d = __ldg(dst + ec);
        int r = __ldg(rel + ec);

        // ---- register counting-sort by r (6 bins) ----
        unsigned b0 = __ballot_sync(FULL, r == 0);
        unsigned b1 = __ballot_sync(FULL, r == 1);
        unsigned b2 = __ballot_sync(FULL, r == 2);
        unsigned b3 = __ballot_sync(FULL, r == 3);
        unsigned b4 = __ballot_sync(FULL, r == 4);
        unsigned b5 = __ballot_sync(FULL, r == 5);

        int t1 = __popc(b0);               // cumulative bin boundaries
        int t2 = t1 + __popc(b1);
        int t3 = t2 + __popc(b2);
        int t4 = t3 + __popc(b3);
        int t5 = t4 + __popc(b4);

        // my sorted slot index == lane; find its bin v and source lane
        int v = (lane >= t1) + (lane >= t2) + (lane >= t3)
              + (lane >= t4) + (lane >= t5);
        int prev; unsigned bv;
        switch (v) {
            case 0:  prev = 0;  bv = b0; break;
            case 1:  prev = t1; bv = b1; break;
            case 2:  prev = t2; bv = b2; break;
            case 3:  prev = t3; bv = b3; break;
            case 4:  prev = t4; bv = b4; break;
            default: prev = t5; bv = b5; break;
        }
        int srcLane = __fns(bv, 0, lane - prev + 1);

        // gather sorted edge data into this lane (slot = lane)
        int s_s  = __shfl_sync(FULL, s, srcLane);
        int d_s  = __shfl_sync(FULL, d, srcLane);
        int eo   = base + srcLane;
        if (eo >= E) eo = E - 1;           // matches clamped data
        int er_s = (eo << 3) | v;          // pack orig edge + relation

        // ---- process 8 quads of sorted slots; W rows now come in runs ----
        #pragma unroll 1
        for (int i = 0; i < 8; i++) {
            int q  = i * 4 + grp;          // sorted slot for my group
            int ss = __shfl_sync(FULL, s_s, q);
            int dd = __shfl_sync(FULL, d_s, q);
            int ee = __shfl_sync(FULL, er_s, q);
            int rr = ee & 7;
            int eoq = ee >> 3;

            const float4* __restrict__ up = h4 + ss * 32 + sub;
            const float4* __restrict__ vp = h4 + dd * 32 + sub;
            const float4* __restrict__ wp = W4 + rr * 32 + sub;

            // Phase 1: float4 positions sub, sub+8 (6 loads batched)
            float4 u0 = __ldg(up);
            float4 u1 = __ldg(up + 8);
            float4 v0 = __ldg(vp);
            float4 v1 = __ldg(vp + 8);
            float4 w0 = __ldg(wp);
            float4 w1 = __ldg(wp + 8);

            float sum = u0.x * w0.x * v0.x
                      + u0.y * w0.y * v0.y
                      + u0.z * w0.z * v0.z
                      + u0.w * w0.w * v0.w
                      + u1.x * w1.x * v1.x
                      + u1.y * w1.y * v1.y
                      + u1.z * w1.z * v1.z
                      + u1.w * w1.w * v1.w;

            // Phase 2: float4 positions sub+16, sub+24
            u0 = __ldg(up + 16);
            u1 = __ldg(up + 24);
            v0 = __ldg(vp + 16);
            v1 = __ldg(vp + 24);
            w0 = __ldg(wp + 16);
            w1 = __ldg(wp + 24);

            sum += u0.x * w0.x * v0.x
                 + u0.y * w0.y * v0.y
                 + u0.z * w0.z * v0.z
                 + u0.w * w0.w * v0.w
                 + u1.x * w1.x * v1.x
                 + u1.y * w1.y * v1.y
                 + u1.z * w1.z * v1.z
                 + u1.w * w1.w * v1.w;

            #pragma unroll
            for (int off = 4; off > 0; off >>= 1)
                sum += __shfl_xor_sync(FULL, sum, off);

            // 4 stores land inside this chunk's 128B out-window: 1 sector
            if (sub == 0)
                out[eoq] = 1.0f / (1.0f + __expf(-sum));
        }
    }
}

extern "C" void kernel_launch(void* const* d_in, const int* in_sizes, int n_in,
                              void* d_out, int out_size)
{
    const float* h   = (const float*)d_in[0];
    const float* W   = (const float*)d_in[1];
    const int*   src = (const int*)d_in[2];
    const int*   dst = (const int*)d_in[3];
    const int*   rel = (const int*)d_in[4];
    float* out = (float*)d_out;

    int E = in_sizes[2];
    if (E <= 0) return;

    int nchunks = (E + 31) >> 5;
    int blocks_needed = (nchunks + WPB - 1) / WPB;
    if (blocks_needed < 1) blocks_needed = 1;
    int blocks = blocks_needed < GRID_BLOCKS ? blocks_needed : GRID_BLOCKS;
    distmult_kernel<<<blocks, TPB>>>(h, W, src, dst, rel, out, E);
}